// round 1
// baseline (speedup 1.0000x reference)
#include <cuda_runtime.h>
#include <cstdint>

// Problem constants
static constexpr int BATCH = 8192;
static constexpr int S     = 3;
static constexpr int D     = 2048;   // input feature dim
static constexpr int DK    = 1024;   // projection dim
static constexpr int ROWS  = BATCH * S;      // 24576 rows per tensor
static constexpr int GM    = ROWS * 2;       // 49152 (img rows then text rows)
static constexpr int GN    = 2 * DK;         // 2048  (Q cols then K cols)
static constexpr int GK    = D;              // 2048
static constexpr float NORM_FACT = 0.03125f; // 1/sqrt(1024)

// Scratch: QK[m, n]  (m: img rows then text rows; n: [Q | K])
__device__ float g_QK[(size_t)GM * GN];

// ---------------------------------------------------------------------------
// Kernel 1: fused projection GEMM
//   QK = X @ Wcat^T + bcat
//   X rows: m < 24576 -> img row m ; else text row m-24576
//   W rows: n < 1024  -> Wq row n  ; else Wk row n-1024
// Classic 128x128x8 register-blocked SGEMM, 8x8 microtile (2x 4-wide frags),
// single-stage register prefetch of the next tile.
// ---------------------------------------------------------------------------
__global__ __launch_bounds__(256, 2) void gemm_qk_kernel(
    const float* __restrict__ img,
    const float* __restrict__ text,
    const float* __restrict__ Wq,
    const float* __restrict__ Wk,
    const float* __restrict__ bq,
    const float* __restrict__ bk)
{
    __shared__ float As[8][128];
    __shared__ float Bs[8][128];

    const int bm = blockIdx.y * 128;
    const int bn = blockIdx.x * 128;

    // Tile is entirely within one source (24576 % 128 == 0, 1024 % 128 == 0)
    const float* Abase = (bm < ROWS) ? (img  + (size_t)bm * D)
                                     : (text + (size_t)(bm - ROWS) * D);
    const float* Bbase = (bn < DK)   ? (Wq + (size_t)bn * D)
                                     : (Wk + (size_t)(bn - DK) * D);

    const int tid  = threadIdx.x;
    const int tx   = tid & 15;       // 0..15 -> N microtiles
    const int ty   = tid >> 4;       // 0..15 -> M microtiles
    const int lrow = tid >> 1;       // 0..127 (load row within tile)
    const int lcol = (tid & 1) * 4;  // 0 or 4 (load col within BK=8)

    const float* Aptr = Abase + (size_t)lrow * D + lcol;
    const float* Bptr = Bbase + (size_t)lrow * D + lcol;

    float c[8][8];
    #pragma unroll
    for (int i = 0; i < 8; i++)
        #pragma unroll
        for (int j = 0; j < 8; j++) c[i][j] = 0.0f;

    // prefetch first tile
    float4 av = *(const float4*)(Aptr);
    float4 bv = *(const float4*)(Bptr);

    for (int k0 = 0; k0 < GK; k0 += 8) {
        __syncthreads();
        As[lcol + 0][lrow] = av.x;
        As[lcol + 1][lrow] = av.y;
        As[lcol + 2][lrow] = av.z;
        As[lcol + 3][lrow] = av.w;
        Bs[lcol + 0][lrow] = bv.x;
        Bs[lcol + 1][lrow] = bv.y;
        Bs[lcol + 2][lrow] = bv.z;
        Bs[lcol + 3][lrow] = bv.w;
        __syncthreads();

        if (k0 + 8 < GK) {
            av = *(const float4*)(Aptr + k0 + 8);
            bv = *(const float4*)(Bptr + k0 + 8);
        }

        #pragma unroll
        for (int k = 0; k < 8; k++) {
            float4 a0 = *(const float4*)&As[k][ty * 4];
            float4 a1 = *(const float4*)&As[k][64 + ty * 4];
            float4 b0 = *(const float4*)&Bs[k][tx * 4];
            float4 b1 = *(const float4*)&Bs[k][64 + tx * 4];
            float ar[8] = {a0.x, a0.y, a0.z, a0.w, a1.x, a1.y, a1.z, a1.w};
            float br[8] = {b0.x, b0.y, b0.z, b0.w, b1.x, b1.y, b1.z, b1.w};
            #pragma unroll
            for (int i = 0; i < 8; i++)
                #pragma unroll
                for (int j = 0; j < 8; j++)
                    c[i][j] += ar[i] * br[j];
        }
    }

    // bias + writeback (float4 stores)
    #pragma unroll
    for (int jh = 0; jh < 2; jh++) {
        const int coln = bn + jh * 64 + tx * 4;   // global col, multiple of 4
        const float* bb = (coln < DK) ? (bq + coln) : (bk + (coln - DK));
        const float4 bias = *(const float4*)bb;
        #pragma unroll
        for (int ih = 0; ih < 2; ih++) {
            #pragma unroll
            for (int i = 0; i < 4; i++) {
                const int row = bm + ih * 64 + ty * 4 + i;
                float4 v;
                v.x = c[ih * 4 + i][jh * 4 + 0] + bias.x;
                v.y = c[ih * 4 + i][jh * 4 + 1] + bias.y;
                v.z = c[ih * 4 + i][jh * 4 + 2] + bias.z;
                v.w = c[ih * 4 + i][jh * 4 + 3] + bias.w;
                *(float4*)&g_QK[(size_t)row * GN + coln] = v;
            }
        }
    }
}

// ---------------------------------------------------------------------------
// Kernel 2: per-batch attention algebra + epilogue
//   1 CTA per batch. 27 warp dot-products (len 1024) -> logits[3][3][3]
//   thread 0: softmax * NORM_FACT, Linear(3,3), Bilinear(3,3,3)
//   all threads: output_i = atten_i @ img[b], output_t = atten_t @ text[b]
// ---------------------------------------------------------------------------
__global__ __launch_bounds__(256) void attn_epilogue_kernel(
    const float* __restrict__ img,
    const float* __restrict__ text,
    const float* __restrict__ Wj,
    const float* __restrict__ bj,
    const float* __restrict__ Wbil,
    float* __restrict__ out)
{
    const int b    = blockIdx.x;
    const int tid  = threadIdx.x;
    const int warp = tid >> 5;
    const int lane = tid & 31;

    __shared__ float logits[3][3][3];   // [map][q][s] map: 0=it 1=ii 2=tt
    __shared__ float attnI[3][3];
    __shared__ float attnT[3][3];

    // 27 dot products over DK=1024
    for (int idx = warp; idx < 27; idx += 8) {
        const int map = idx / 9;
        const int r   = idx % 9;
        const int q   = r / 3;
        const int s   = r % 3;

        // row bases in g_QK
        const size_t mi_q = (size_t)(b * 3 + q) * GN;          // img row q
        const size_t mi_s = (size_t)(b * 3 + s) * GN;          // img row s
        const size_t mt_q = (size_t)(ROWS + b * 3 + q) * GN;   // text row q
        const size_t mt_s = (size_t)(ROWS + b * 3 + s) * GN;   // text row s

        const float* a;
        const float* v;
        if (map == 0) {        // Q_i[q] . K_t[s]
            a = g_QK + mi_q;        v = g_QK + mt_s + DK;
        } else if (map == 1) { // Q_i[q] . K_i[s]
            a = g_QK + mi_q;        v = g_QK + mi_s + DK;
        } else {               // Q_t[q] . K_t[s]
            a = g_QK + mt_q;        v = g_QK + mt_s + DK;
        }

        float sum = 0.0f;
        for (int t = lane; t < DK; t += 32)
            sum += a[t] * v[t];
        #pragma unroll
        for (int off = 16; off > 0; off >>= 1)
            sum += __shfl_xor_sync(0xFFFFFFFFu, sum, off);
        if (lane == 0) logits[map][q][s] = sum;
    }
    __syncthreads();

    if (tid == 0) {
        float p[3][3][3];
        // softmax over s, then * NORM_FACT (scale after softmax, per reference)
        #pragma unroll
        for (int map = 0; map < 3; map++) {
            #pragma unroll
            for (int q = 0; q < 3; q++) {
                float m = logits[map][q][0];
                m = fmaxf(m, logits[map][q][1]);
                m = fmaxf(m, logits[map][q][2]);
                float e0 = __expf(logits[map][q][0] - m);
                float e1 = __expf(logits[map][q][1] - m);
                float e2 = __expf(logits[map][q][2] - m);
                float inv = NORM_FACT / (e0 + e1 + e2);
                p[map][q][0] = e0 * inv;
                p[map][q][1] = e1 * inv;
                p[map][q][2] = e2 * inv;
            }
        }
        // j_lin: jl[map][q][o] = sum_s p[map][q][s] * Wj[o*3+s] + bj[o]
        float jl[3][3][3];
        #pragma unroll
        for (int map = 0; map < 3; map++)
            #pragma unroll
            for (int q = 0; q < 3; q++)
                #pragma unroll
                for (int o = 0; o < 3; o++)
                    jl[map][q][o] = p[map][q][0] * Wj[o * 3 + 0]
                                  + p[map][q][1] * Wj[o * 3 + 1]
                                  + p[map][q][2] * Wj[o * 3 + 2]
                                  + bj[o];
        // bilinear: atten[q][o] = sum_{i,j} x1[q][i] * Wbil[o*9+i*3+j] * x2[q][j]
        #pragma unroll
        for (int q = 0; q < 3; q++) {
            #pragma unroll
            for (int o = 0; o < 3; o++) {
                float accI = 0.0f, accT = 0.0f;
                #pragma unroll
                for (int i = 0; i < 3; i++) {
                    #pragma unroll
                    for (int j = 0; j < 3; j++) {
                        const float w = Wbil[o * 9 + i * 3 + j];
                        accI += jl[0][q][i] * w * jl[1][q][j];
                        accT += jl[0][q][i] * w * jl[2][q][j];
                    }
                }
                attnI[q][o] = accI;
                attnT[q][o] = accT;
            }
        }
    }
    __syncthreads();

    // epilogue: out_i[q, d] = sum_s attnI[q][s] * img[b,s,d]  (text likewise)
    const float* ib = img  + (size_t)b * 3 * D;
    const float* tb = text + (size_t)b * 3 * D;
    float* oi = out + (size_t)(b * 3) * D;
    float* ot = out + (size_t)ROWS * D + (size_t)(b * 3) * D;

    const float ai00 = attnI[0][0], ai01 = attnI[0][1], ai02 = attnI[0][2];
    const float ai10 = attnI[1][0], ai11 = attnI[1][1], ai12 = attnI[1][2];
    const float ai20 = attnI[2][0], ai21 = attnI[2][1], ai22 = attnI[2][2];
    const float at00 = attnT[0][0], at01 = attnT[0][1], at02 = attnT[0][2];
    const float at10 = attnT[1][0], at11 = attnT[1][1], at12 = attnT[1][2];
    const float at20 = attnT[2][0], at21 = attnT[2][1], at22 = attnT[2][2];

    for (int d = tid; d < D; d += 256) {
        const float i0 = ib[d], i1 = ib[D + d], i2 = ib[2 * D + d];
        const float t0 = tb[d], t1 = tb[D + d], t2 = tb[2 * D + d];
        oi[0 * D + d] = ai00 * i0 + ai01 * i1 + ai02 * i2;
        oi[1 * D + d] = ai10 * i0 + ai11 * i1 + ai12 * i2;
        oi[2 * D + d] = ai20 * i0 + ai21 * i1 + ai22 * i2;
        ot[0 * D + d] = at00 * t0 + at01 * t1 + at02 * t2;
        ot[1 * D + d] = at10 * t0 + at11 * t1 + at12 * t2;
        ot[2 * D + d] = at20 * t0 + at21 * t1 + at22 * t2;
    }
}

// ---------------------------------------------------------------------------
extern "C" void kernel_launch(void* const* d_in, const int* in_sizes, int n_in,
                              void* d_out, int out_size)
{
    const float* img  = (const float*)d_in[0];
    const float* text = (const float*)d_in[1];
    const float* Wq   = (const float*)d_in[2];
    const float* bq   = (const float*)d_in[3];
    const float* Wk   = (const float*)d_in[4];
    const float* bk   = (const float*)d_in[5];
    const float* Wj   = (const float*)d_in[6];
    const float* bj   = (const float*)d_in[7];
    const float* Wbil = (const float*)d_in[8];
    float* out = (float*)d_out;

    dim3 grid(GN / 128, GM / 128);   // 16 x 384
    gemm_qk_kernel<<<grid, 256>>>(img, text, Wq, Wk, bq, bk);
    attn_epilogue_kernel<<<BATCH, 256>>>(img, text, Wj, bj, Wbil, out);
}

// round 3
// speedup vs baseline: 1.6139x; 1.6139x over previous
#include <cuda_runtime.h>
#include <cuda_bf16.h>
#include <cstdint>

// ---------------------------------------------------------------------------
// Problem constants
// ---------------------------------------------------------------------------
static constexpr int BATCH = 8192;
static constexpr int D     = 2048;           // input feature dim (K of GEMM)
static constexpr int DK    = 1024;           // projection dim
static constexpr int ROWS  = BATCH * 3;      // 24576 rows per tensor
static constexpr int GM    = ROWS * 2;       // 49152 (img rows then text rows)
static constexpr int GN    = 2 * DK;         // 2048  (Q cols then K cols)
static constexpr int GK    = D;              // 2048
static constexpr float NORM_FACT = 0.03125f; // 1/sqrt(1024)

// GEMM tiling
static constexpr int TILE_M = 128;
static constexpr int TILE_N = 128;
static constexpr int BK     = 64;            // bf16 elems per chunk (128B rows)
static constexpr int NCHUNK = GK / BK;       // 32
static constexpr int NSTAGE = 3;

static constexpr int OP_TILE_BYTES = 128 * 128;          // one operand tile: 128 rows x 128B
static constexpr int STAGE_BYTES   = 4 * OP_TILE_BYTES;  // Ah, Al, Bh, Bl = 64KB
static constexpr int SMEM_TOTAL    = NSTAGE * STAGE_BYTES; // 192KB

// ---------------------------------------------------------------------------
// Device scratch
// ---------------------------------------------------------------------------
__device__ __align__(16) __nv_bfloat16 g_Ah[(size_t)GM * GK];
__device__ __align__(16) __nv_bfloat16 g_Al[(size_t)GM * GK];
__device__ __align__(16) __nv_bfloat16 g_Bh[(size_t)GN * GK];
__device__ __align__(16) __nv_bfloat16 g_Bl[(size_t)GN * GK];
__device__ __align__(16) float         g_QK[(size_t)GM * GN];

// ---------------------------------------------------------------------------
// PTX helpers (sm_80-era portable ISA only: cp.async, ldmatrix, mma.sync)
// ---------------------------------------------------------------------------
__device__ __forceinline__ uint32_t smem_u32(const void* p) {
    uint32_t a;
    asm("{ .reg .u64 t; cvta.to.shared.u64 t, %1; cvt.u32.u64 %0, t; }" : "=r"(a) : "l"(p));
    return a;
}
__device__ __forceinline__ void cp16(uint32_t dst, const void* src) {
    asm volatile("cp.async.cg.shared.global [%0], [%1], 16;" :: "r"(dst), "l"(src));
}
__device__ __forceinline__ void cp_commit() {
    asm volatile("cp.async.commit_group;" ::: "memory");
}
template <int N>
__device__ __forceinline__ void cp_wait() {
    asm volatile("cp.async.wait_group %0;" :: "n"(N) : "memory");
}
__device__ __forceinline__ void ldmx4(uint32_t* r, uint32_t addr) {
    asm volatile("ldmatrix.sync.aligned.m8n8.x4.shared.b16 {%0,%1,%2,%3}, [%4];"
                 : "=r"(r[0]), "=r"(r[1]), "=r"(r[2]), "=r"(r[3]) : "r"(addr));
}
__device__ __forceinline__ void mma_bf16(float* c, const uint32_t* a, uint32_t b0, uint32_t b1) {
    asm volatile(
        "mma.sync.aligned.m16n8k16.row.col.f32.bf16.bf16.f32 "
        "{%0,%1,%2,%3}, {%4,%5,%6,%7}, {%8,%9}, {%0,%1,%2,%3};"
        : "+f"(c[0]), "+f"(c[1]), "+f"(c[2]), "+f"(c[3])
        : "r"(a[0]), "r"(a[1]), "r"(a[2]), "r"(a[3]), "r"(b0), "r"(b1));
}

// ---------------------------------------------------------------------------
// Convert kernels: fp32 -> bf16 hi + lo residual
// ---------------------------------------------------------------------------
__global__ void convertA_kernel(const float* __restrict__ img, const float* __restrict__ text) {
    const size_t i = (size_t)blockIdx.x * blockDim.x + threadIdx.x;     // float4 index
    const size_t half = (size_t)ROWS * GK / 4;
    const float4 v = (i < half) ? ((const float4*)img)[i] : ((const float4*)text)[i - half];
    __nv_bfloat16 h0 = __float2bfloat16_rn(v.x), h1 = __float2bfloat16_rn(v.y);
    __nv_bfloat16 h2 = __float2bfloat16_rn(v.z), h3 = __float2bfloat16_rn(v.w);
    __nv_bfloat162* ah = (__nv_bfloat162*)g_Ah;
    __nv_bfloat162* al = (__nv_bfloat162*)g_Al;
    ah[2 * i]     = __nv_bfloat162(h0, h1);
    ah[2 * i + 1] = __nv_bfloat162(h2, h3);
    al[2 * i]     = __nv_bfloat162(__float2bfloat16_rn(v.x - __bfloat162float(h0)),
                                   __float2bfloat16_rn(v.y - __bfloat162float(h1)));
    al[2 * i + 1] = __nv_bfloat162(__float2bfloat16_rn(v.z - __bfloat162float(h2)),
                                   __float2bfloat16_rn(v.w - __bfloat162float(h3)));
}

__global__ void convertB_kernel(const float* __restrict__ Wq, const float* __restrict__ Wk) {
    const size_t i = (size_t)blockIdx.x * blockDim.x + threadIdx.x;     // float4 index
    const size_t half = (size_t)DK * GK / 4;
    const float4 v = (i < half) ? ((const float4*)Wq)[i] : ((const float4*)Wk)[i - half];
    __nv_bfloat16 h0 = __float2bfloat16_rn(v.x), h1 = __float2bfloat16_rn(v.y);
    __nv_bfloat16 h2 = __float2bfloat16_rn(v.z), h3 = __float2bfloat16_rn(v.w);
    __nv_bfloat162* bh = (__nv_bfloat162*)g_Bh;
    __nv_bfloat162* bl = (__nv_bfloat162*)g_Bl;
    bh[2 * i]     = __nv_bfloat162(h0, h1);
    bh[2 * i + 1] = __nv_bfloat162(h2, h3);
    bl[2 * i]     = __nv_bfloat162(__float2bfloat16_rn(v.x - __bfloat162float(h0)),
                                   __float2bfloat16_rn(v.y - __bfloat162float(h1)));
    bl[2 * i + 1] = __nv_bfloat162(__float2bfloat16_rn(v.z - __bfloat162float(h2)),
                                   __float2bfloat16_rn(v.w - __bfloat162float(h3)));
}

// ---------------------------------------------------------------------------
// mma.sync split-bf16 GEMM: g_QK = A @ B^T + bias  (3 terms: hh + hl + lh)
// 128x128 CTA tile, 8 warps (2x4), 64x32 warp tile, BK=64, 3-stage cp.async.
// ---------------------------------------------------------------------------
__global__ void __launch_bounds__(256, 1) gemm_mma_kernel(
    const float* __restrict__ bq, const float* __restrict__ bk)
{
    extern __shared__ char smem[];
    const uint32_t sbase = smem_u32(smem);
    const int tid  = threadIdx.x;
    const int warp = tid >> 5;
    const int lane = tid & 31;

    const int bm = blockIdx.y * TILE_M;
    const int bn = blockIdx.x * TILE_N;
    const int wm = warp & 1;     // M half (64 rows)
    const int wn = warp >> 1;    // N quarter (32 cols)

    // ---- load geometry: thread -> (row, 4 consecutive 16B chunks) ----
    const int lr  = tid >> 1;          // 0..127
    const int lc0 = (tid & 1) * 4;     // first 16B chunk (0 or 4) of this row
    const __nv_bfloat16* gAh = g_Ah + (size_t)(bm + lr) * GK + lc0 * 8;
    const __nv_bfloat16* gAl = g_Al + (size_t)(bm + lr) * GK + lc0 * 8;
    const __nv_bfloat16* gBh = g_Bh + (size_t)(bn + lr) * GK + lc0 * 8;
    const __nv_bfloat16* gBl = g_Bl + (size_t)(bn + lr) * GK + lc0 * 8;

    uint32_t swoff[4];   // swizzled smem byte offsets for the 4 chunks
    #pragma unroll
    for (int i = 0; i < 4; i++)
        swoff[i] = (uint32_t)(lr * 128 + (((lc0 + i) ^ (lr & 7)) * 16));

    auto load_stage = [&](int c, int s) {
        const uint32_t st = sbase + s * STAGE_BYTES;
        const size_t kof = (size_t)c * BK;   // elems
        #pragma unroll
        for (int i = 0; i < 4; i++) {
            cp16(st +                     swoff[i], gAh + kof + i * 8);
            cp16(st +     OP_TILE_BYTES + swoff[i], gAl + kof + i * 8);
            cp16(st + 2 * OP_TILE_BYTES + swoff[i], gBh + kof + i * 8);
            cp16(st + 3 * OP_TILE_BYTES + swoff[i], gBl + kof + i * 8);
        }
        cp_commit();
    };

    // ---- prologue: fill all stages ----
    #pragma unroll
    for (int s = 0; s < NSTAGE; s++) load_stage(s, s);

    // ---- per-warp ldmatrix addressing ----
    const int lrow = lane & 15;
    const int lsel = lane >> 4;
    uint32_t swz[4];   // per k-step (k16) swizzled offset for lane
    #pragma unroll
    for (int ks = 0; ks < 4; ks++)
        swz[ks] = (uint32_t)(lrow * 128 + (((ks * 2 + lsel) ^ (lrow & 7)) * 16));

    const uint32_t aWarp = sbase + (uint32_t)(wm * 64) * 128;                     // within Ah
    const uint32_t bWarp = sbase + 2 * OP_TILE_BYTES + (uint32_t)(wn * 32) * 128; // within Bh

    float acc[4][4][4];
    #pragma unroll
    for (int i = 0; i < 4; i++)
        #pragma unroll
        for (int j = 0; j < 4; j++)
            #pragma unroll
            for (int k = 0; k < 4; k++) acc[i][j][k] = 0.0f;

    for (int c = 0; c < NCHUNK; c++) {
        const int s = c % NSTAGE;
        cp_wait<NSTAGE - 1>();
        __syncthreads();

        const uint32_t aS = aWarp + s * STAGE_BYTES;
        const uint32_t bS = bWarp + s * STAGE_BYTES;

        #pragma unroll
        for (int ks = 0; ks < 4; ks++) {
            uint32_t ah[4][4], al[4][4], bh[2][4], bl[2][4];
            #pragma unroll
            for (int mf = 0; mf < 4; mf++) {
                ldmx4(ah[mf], aS + mf * 2048 + swz[ks]);
                ldmx4(al[mf], aS + OP_TILE_BYTES + mf * 2048 + swz[ks]);
            }
            #pragma unroll
            for (int nf2 = 0; nf2 < 2; nf2++) {
                ldmx4(bh[nf2], bS + nf2 * 2048 + swz[ks]);
                ldmx4(bl[nf2], bS + OP_TILE_BYTES + nf2 * 2048 + swz[ks]);
            }
            #pragma unroll
            for (int mf = 0; mf < 4; mf++) {
                #pragma unroll
                for (int nf = 0; nf < 4; nf++) {
                    const int nf2 = nf >> 1, sub = nf & 1;
                    mma_bf16(acc[mf][nf], ah[mf], bh[nf2][sub], bh[nf2][sub + 2]); // hh
                    mma_bf16(acc[mf][nf], ah[mf], bl[nf2][sub], bl[nf2][sub + 2]); // hl
                    mma_bf16(acc[mf][nf], al[mf], bh[nf2][sub], bh[nf2][sub + 2]); // lh
                }
            }
        }

        __syncthreads();   // all warps done reading stage s before overwrite
        if (c + NSTAGE < NCHUNK) load_stage(c + NSTAGE, s);
        else                     cp_commit();   // empty group keeps wait_group math valid
    }

    // ---- epilogue: bias + writeback ----
    const int trow = lane >> 2;
    const int tcol = (lane & 3) * 2;
    const bool isQ = (bn < DK);
    const float* bias = isQ ? bq : bk;
    const int bcol0 = isQ ? bn : (bn - DK);

    #pragma unroll
    for (int mf = 0; mf < 4; mf++) {
        const int r0 = bm + wm * 64 + mf * 16 + trow;
        #pragma unroll
        for (int nf = 0; nf < 4; nf++) {
            const int coln = wn * 32 + nf * 8 + tcol;  // within tile
            const float2 bv = *(const float2*)(bias + bcol0 + coln);
            float2 v0, v1;
            v0.x = acc[mf][nf][0] + bv.x;
            v0.y = acc[mf][nf][1] + bv.y;
            v1.x = acc[mf][nf][2] + bv.x;
            v1.y = acc[mf][nf][3] + bv.y;
            *(float2*)&g_QK[(size_t)r0 * GN + bn + coln]       = v0;
            *(float2*)&g_QK[(size_t)(r0 + 8) * GN + bn + coln] = v1;
        }
    }
}

// ---------------------------------------------------------------------------
// Kernel: per-batch attention algebra + output epilogue
// ---------------------------------------------------------------------------
__global__ void __launch_bounds__(256) attn_epilogue_kernel(
    const float* __restrict__ img,
    const float* __restrict__ text,
    const float* __restrict__ Wj,
    const float* __restrict__ bj,
    const float* __restrict__ Wbil,
    float* __restrict__ out)
{
    const int b    = blockIdx.x;
    const int tid  = threadIdx.x;
    const int warp = tid >> 5;
    const int lane = tid & 31;

    __shared__ float logits[3][3][3];
    __shared__ float attnI[3][3];
    __shared__ float attnT[3][3];

    for (int idx = warp; idx < 27; idx += 8) {
        const int map = idx / 9;
        const int r   = idx % 9;
        const int q   = r / 3;
        const int s   = r % 3;

        const size_t mi_q = (size_t)(b * 3 + q) * GN;
        const size_t mi_s = (size_t)(b * 3 + s) * GN;
        const size_t mt_q = (size_t)(ROWS + b * 3 + q) * GN;
        const size_t mt_s = (size_t)(ROWS + b * 3 + s) * GN;

        const float* a;
        const float* v;
        if (map == 0)      { a = g_QK + mi_q; v = g_QK + mt_s + DK; }
        else if (map == 1) { a = g_QK + mi_q; v = g_QK + mi_s + DK; }
        else               { a = g_QK + mt_q; v = g_QK + mt_s + DK; }

        float sum = 0.0f;
        for (int t = lane; t < DK; t += 32)
            sum += a[t] * v[t];
        #pragma unroll
        for (int off = 16; off > 0; off >>= 1)
            sum += __shfl_xor_sync(0xFFFFFFFFu, sum, off);
        if (lane == 0) logits[map][q][s] = sum;
    }
    __syncthreads();

    if (tid == 0) {
        float p[3][3][3];
        #pragma unroll
        for (int map = 0; map < 3; map++) {
            #pragma unroll
            for (int q = 0; q < 3; q++) {
                float m = logits[map][q][0];
                m = fmaxf(m, logits[map][q][1]);
                m = fmaxf(m, logits[map][q][2]);
                float e0 = __expf(logits[map][q][0] - m);
                float e1 = __expf(logits[map][q][1] - m);
                float e2 = __expf(logits[map][q][2] - m);
                float inv = NORM_FACT / (e0 + e1 + e2);
                p[map][q][0] = e0 * inv;
                p[map][q][1] = e1 * inv;
                p[map][q][2] = e2 * inv;
            }
        }
        float jl[3][3][3];
        #pragma unroll
        for (int map = 0; map < 3; map++)
            #pragma unroll
            for (int q = 0; q < 3; q++)
                #pragma unroll
                for (int o = 0; o < 3; o++)
                    jl[map][q][o] = p[map][q][0] * Wj[o * 3 + 0]
                                  + p[map][q][1] * Wj[o * 3 + 1]
                                  + p[map][q][2] * Wj[o * 3 + 2]
                                  + bj[o];
        #pragma unroll
        for (int q = 0; q < 3; q++) {
            #pragma unroll
            for (int o = 0; o < 3; o++) {
                float accI = 0.0f, accT = 0.0f;
                #pragma unroll
                for (int i = 0; i < 3; i++) {
                    #pragma unroll
                    for (int jx = 0; jx < 3; jx++) {
                        const float w = Wbil[o * 9 + i * 3 + jx];
                        accI += jl[0][q][i] * w * jl[1][q][jx];
                        accT += jl[0][q][i] * w * jl[2][q][jx];
                    }
                }
                attnI[q][o] = accI;
                attnT[q][o] = accT;
            }
        }
    }
    __syncthreads();

    const float* ib = img  + (size_t)b * 3 * D;
    const float* tb = text + (size_t)b * 3 * D;
    float* oi = out + (size_t)(b * 3) * D;
    float* ot = out + (size_t)ROWS * D + (size_t)(b * 3) * D;

    const float ai00 = attnI[0][0], ai01 = attnI[0][1], ai02 = attnI[0][2];
    const float ai10 = attnI[1][0], ai11 = attnI[1][1], ai12 = attnI[1][2];
    const float ai20 = attnI[2][0], ai21 = attnI[2][1], ai22 = attnI[2][2];
    const float at00 = attnT[0][0], at01 = attnT[0][1], at02 = attnT[0][2];
    const float at10 = attnT[1][0], at11 = attnT[1][1], at12 = attnT[1][2];
    const float at20 = attnT[2][0], at21 = attnT[2][1], at22 = attnT[2][2];

    for (int d = tid; d < D; d += 256) {
        const float i0 = ib[d], i1 = ib[D + d], i2 = ib[2 * D + d];
        const float t0 = tb[d], t1 = tb[D + d], t2 = tb[2 * D + d];
        oi[0 * D + d] = ai00 * i0 + ai01 * i1 + ai02 * i2;
        oi[1 * D + d] = ai10 * i0 + ai11 * i1 + ai12 * i2;
        oi[2 * D + d] = ai20 * i0 + ai21 * i1 + ai22 * i2;
        ot[0 * D + d] = at00 * t0 + at01 * t1 + at02 * t2;
        ot[1 * D + d] = at10 * t0 + at11 * t1 + at12 * t2;
        ot[2 * D + d] = at20 * t0 + at21 * t1 + at22 * t2;
    }
}

// ---------------------------------------------------------------------------
extern "C" void kernel_launch(void* const* d_in, const int* in_sizes, int n_in,
                              void* d_out, int out_size)
{
    const float* img  = (const float*)d_in[0];
    const float* text = (const float*)d_in[1];
    const float* Wq   = (const float*)d_in[2];
    const float* bq   = (const float*)d_in[3];
    const float* Wk   = (const float*)d_in[4];
    const float* bk   = (const float*)d_in[5];
    const float* Wj   = (const float*)d_in[6];
    const float* bj   = (const float*)d_in[7];
    const float* Wbil = (const float*)d_in[8];
    float* out = (float*)d_out;

    cudaFuncSetAttribute(gemm_mma_kernel,
                         cudaFuncAttributeMaxDynamicSharedMemorySize, SMEM_TOTAL);

    {   // convert inputs to bf16 hi/lo
        const size_t n4a = (size_t)GM * GK / 4;
        convertA_kernel<<<(unsigned)(n4a / 256), 256>>>(img, text);
        const size_t n4b = (size_t)GN * GK / 4;
        convertB_kernel<<<(unsigned)(n4b / 256), 256>>>(Wq, Wk);
    }

    dim3 grid(GN / TILE_N, GM / TILE_M);   // 16 x 384
    gemm_mma_kernel<<<grid, 256, SMEM_TOTAL>>>(bq, bk);

    attn_epilogue_kernel<<<BATCH, 256>>>(img, text, Wj, bj, Wbil, out);
}